// round 12
// baseline (speedup 1.0000x reference)
#include <cuda_runtime.h>
#include <cuda_fp16.h>
#include <cstdint>

// Problem constants (fixed by the dataset)
#define B_   4
#define NQ_  16384
#define C_   256
#define NH_  8
#define NP_  4
#define H_   128
#define W_   128
#define HD_  32
#define M_   (B_ * NQ_)      // 65536 rows
#define HW_  (H_ * W_)       // 16384

// Scratch (__device__ globals: allocation-free rule)
__device__ float  g_qp       [(size_t)M_ * 96];        // [M, 64 off(pre-scaled) | 32 logits]
__device__ __half g_vproj_h  [(size_t)B_ * HW_ * C_];  // [B, HW, C] fp16
__device__ __half g_sampled_h[(size_t)M_ * C_];        // [M, C] fp16
__device__ __half g_Wqpt_h   [96 * 256];               // packed W_off*s|W_attn, [N,K] fp16
__device__ float  g_bqp      [96];
__device__ __half g_Wvt_h    [256 * 256];              // W_v^T  [N,K] fp16
__device__ __half g_Wot_h    [256 * 256];              // W_out^T [N,K] fp16

__device__ __forceinline__ uint32_t smem_u32(const void* p) {
    uint32_t a;
    asm("{ .reg .u64 t; cvta.to.shared.u64 t, %1; cvt.u32.u64 %0, t; }" : "=r"(a) : "l"(p));
    return a;
}
__device__ __forceinline__ void cp16(uint32_t dst, const void* src) {
    asm volatile("cp.async.cg.shared.global [%0], [%1], 16;" :: "r"(dst), "l"(src));
}
__device__ __forceinline__ uint32_t pack_h2(float lo, float hi) {
    uint32_t r;
    asm("cvt.rn.f16x2.f32 %0, %1, %2;" : "=r"(r) : "f"(hi), "f"(lo));
    return r;
}

// m16n8k16 fp16 MMA, fp32 accumulate
__device__ __forceinline__ void mma_h(float* d, const uint32_t* a, const uint32_t* b) {
    asm volatile(
        "mma.sync.aligned.m16n8k16.row.col.f32.f16.f16.f32 "
        "{%0,%1,%2,%3}, {%4,%5,%6,%7}, {%8,%9}, {%0,%1,%2,%3};"
        : "+f"(d[0]), "+f"(d[1]), "+f"(d[2]), "+f"(d[3])
        : "r"(a[0]), "r"(a[1]), "r"(a[2]), "r"(a[3]), "r"(b[0]), "r"(b[1]));
}

// ---------------------------------------------------------------------------
// Single pack kernel. Offset weights/bias pre-scaled by 0.1/128.
// ---------------------------------------------------------------------------
__global__ void pack_all(const float* __restrict__ W_v, const float* __restrict__ W_out,
                         const float* __restrict__ W_off, const float* __restrict__ b_off,
                         const float* __restrict__ W_attn, const float* __restrict__ b_attn)
{
    const float SC = 0.1f / 128.f;
    int idx = blockIdx.x * 256 + threadIdx.x;            // [0, 155648)
    if (idx < 65536) {                                   // W_v^T
        int n = idx >> 8, k = idx & 255;
        g_Wvt_h[idx] = __float2half_rn(W_v[k * 256 + n]);
    } else if (idx < 131072) {                           // W_out^T
        int t = idx - 65536;
        int n = t >> 8, k = t & 255;
        g_Wot_h[t] = __float2half_rn(W_out[k * 256 + n]);
    } else if (idx < 155648) {                           // Wqp^T packed
        int t = idx - 131072;                            // [0, 96*256)
        int n = t >> 8, k = t & 255;
        float v = (n < 64) ? W_off[k * 64 + n] * SC : W_attn[k * 32 + (n - 64)];
        g_Wqpt_h[t] = __float2half_rn(v);
        if (t < 96)
            g_bqp[t] = (t < 64) ? b_off[t] * SC : b_attn[t - 64];
    }
}

// ---------------------------------------------------------------------------
// GEMM body (round-8 measured-best config). Block tile 128 x (16*JT),
// 128 threads = 4 warps (2M x 2N), warp tile 64 x (8*JT). B fp16 in smem;
// A fp32 (cvt at frag load) or fp16 (AHALF). Output fp32 or fp16 (CHALF).
// 3-stage cp.async pipeline, two syncs per K=32 chunk.
// ---------------------------------------------------------------------------
template<int JT, bool AHALF, bool CHALF>
__device__ __forceinline__ void gemm_body(
    const void* __restrict__ Av, const __half* __restrict__ Bt,
    const float* __restrict__ bias, void* __restrict__ Cv, int Ncols,
    int bm, int bn, char* smraw)
{
    constexpr int BN = 16 * JT;
    constexpr int AROWB = AHALF ? 80 : 160;       // bytes per A smem row (pitch 40 elems)
    constexpr int ASTAGE = 128 * AROWB;
    constexpr int BSTAGE = BN * 80;               // pitch 40 halves

    char* Abuf = smraw;
    char* Bbuf = smraw + 3 * ASTAGE;
    const uint32_t AsU = smem_u32(Abuf);
    const uint32_t BsU = smem_u32(Bbuf);

    const int tid  = threadIdx.x;
    const int lane = tid & 31;
    const int wid  = tid >> 5;
    const int wm = (wid & 1) * 64;
    const int wn = (wid >> 1) * (8 * JT);

    const int qr = lane >> 2;           // 0..7
    const int qc = lane & 3;            // 0..3

    const float*  Af = (const float*)Av  + (size_t)bm * 256;
    const __half* Ah = (const __half*)Av + (size_t)bm * 256;
    const __half* Bbase = Bt + (size_t)bn * 256;

    float acc[4][JT][4];
    #pragma unroll
    for (int i = 0; i < 4; i++)
        #pragma unroll
        for (int j = 0; j < JT; j++)
            #pragma unroll
            for (int q = 0; q < 4; q++) acc[i][j][q] = 0.f;

    auto issue_chunk = [&](int c, int buf) {
        const uint32_t ab = AsU + buf * ASTAGE;
        const uint32_t bb = BsU + buf * BSTAGE;
        if (AHALF) {
            #pragma unroll
            for (int o = 0; o < 4; o++) {
                const int u = tid + o * 128;
                const int row = u >> 2, seg = u & 3;
                cp16(ab + row * 80 + seg * 16,
                     Ah + (size_t)row * 256 + c * 32 + seg * 8);
            }
        } else {
            #pragma unroll
            for (int o = 0; o < 8; o++) {
                const int u = tid + o * 128;
                const int row = u >> 3, seg = u & 7;
                cp16(ab + row * 160 + seg * 16,
                     Af + (size_t)row * 256 + c * 32 + seg * 4);
            }
        }
        #pragma unroll
        for (int o = 0; o < BN / 32; o++) {
            const int u = tid + o * 128;
            const int row = u >> 2, seg = u & 3;
            cp16(bb + row * 80 + seg * 16,
                 Bbase + (size_t)row * 256 + c * 32 + seg * 8);
        }
        asm volatile("cp.async.commit_group;");
    };

    issue_chunk(0, 0);
    issue_chunk(1, 1);

    #pragma unroll 1
    for (int c = 0; c < 8; c++) {
        __syncthreads();
        if (c + 2 < 8) issue_chunk(c + 2, (c + 2) % 3);
        if (c < 6)      { asm volatile("cp.async.wait_group 2;"); }
        else if (c == 6){ asm volatile("cp.async.wait_group 1;"); }
        else            { asm volatile("cp.async.wait_group 0;"); }
        __syncthreads();

        const char*   Ac = Abuf + (c % 3) * ASTAGE;
        const __half* Bc = (const __half*)(Bbuf + (c % 3) * BSTAGE);

        #pragma unroll
        for (int ks = 0; ks < 2; ks++) {
            const int kc = ks * 16;
            uint32_t af[4][4], bf[JT][2];
            #pragma unroll
            for (int i = 0; i < 4; i++) {
                if (AHALF) {
                    const __half* ap = (const __half*)Ac + (wm + i * 16 + qr) * 40 + kc + 2 * qc;
                    af[i][0] = *(const uint32_t*)(ap);
                    af[i][1] = *(const uint32_t*)(ap + 8 * 40);
                    af[i][2] = *(const uint32_t*)(ap + 8);
                    af[i][3] = *(const uint32_t*)(ap + 8 * 40 + 8);
                } else {
                    const float* ap = (const float*)Ac + (wm + i * 16 + qr) * 40 + kc + 2 * qc;
                    float2 p0 = *(const float2*)(ap);
                    float2 p1 = *(const float2*)(ap + 8 * 40);
                    float2 p2 = *(const float2*)(ap + 8);
                    float2 p3 = *(const float2*)(ap + 8 * 40 + 8);
                    af[i][0] = pack_h2(p0.x, p0.y);
                    af[i][1] = pack_h2(p1.x, p1.y);
                    af[i][2] = pack_h2(p2.x, p2.y);
                    af[i][3] = pack_h2(p3.x, p3.y);
                }
            }
            #pragma unroll
            for (int j = 0; j < JT; j++) {
                const __half* bp = Bc + (wn + j * 8 + qr) * 40 + kc + 2 * qc;
                bf[j][0] = *(const uint32_t*)(bp);
                bf[j][1] = *(const uint32_t*)(bp + 8);
            }
            #pragma unroll
            for (int i = 0; i < 4; i++)
                #pragma unroll
                for (int j = 0; j < JT; j++)
                    mma_h(acc[i][j], af[i], bf[j]);
        }
    }

    #pragma unroll
    for (int i = 0; i < 4; i++) {
        const int r0 = bm + wm + i * 16 + qr;
        #pragma unroll
        for (int j = 0; j < JT; j++) {
            const int col = bn + wn + j * 8 + qc * 2;
            const float b0 = __ldg(&bias[col]), b1 = __ldg(&bias[col + 1]);
            const float v00 = acc[i][j][0] + b0, v01 = acc[i][j][1] + b1;
            const float v10 = acc[i][j][2] + b0, v11 = acc[i][j][3] + b1;
            if (CHALF) {
                __half* Ch = (__half*)Cv;
                *(uint32_t*)(Ch + (size_t)r0 * Ncols + col)       = pack_h2(v00, v01);
                *(uint32_t*)(Ch + (size_t)(r0 + 8) * Ncols + col) = pack_h2(v10, v11);
            } else {
                float* Cf = (float*)Cv;
                *(float2*)(Cf + (size_t)r0 * Ncols + col)       = make_float2(v00, v01);
                *(float2*)(Cf + (size_t)(r0 + 8) * Ncols + col) = make_float2(v10, v11);
            }
        }
    }
}

static constexpr int SMEM_QPVP = 3 * (128 * 160 + 128 * 80);  // 92160 (vp >= qp stage)
static constexpr int SMEM_OUT  = 3 * (128 * 80  + 128 * 80);  // 61440

// Fused qp + vproj GEMM: grid (3, 512). x 0,1 -> vproj N-tiles; x 2 -> qp.
// Consecutive blockIds interleave both kernels' CTAs on each SM so the two
// latency-bound workloads fill each other's stall bubbles.
__global__ __launch_bounds__(128, 2) void fused_qpvp(
    const float* __restrict__ query, const float* __restrict__ value,
    const float* __restrict__ b_v)
{
    extern __shared__ char smraw[];
    if (blockIdx.x < 2)
        gemm_body<8, false, true>(value, g_Wvt_h, b_v, g_vproj_h, 256,
                                  blockIdx.y * 128, blockIdx.x * 128, smraw);
    else
        gemm_body<6, false, false>(query, g_Wqpt_h, g_bqp, g_qp, 96,
                                   blockIdx.y * 128, 0, smraw);
}

// Output projection (A fp16 sampled -> fp32 out)
__global__ __launch_bounds__(128, 2) void out_gemm(const float* __restrict__ b_out,
                                                   float* __restrict__ out)
{
    extern __shared__ char smraw[];
    gemm_body<8, true, false>(g_sampled_h, g_Wot_h, b_out, out, 256,
                              blockIdx.y * 128, blockIdx.x * 128, smraw);
}

// ---------------------------------------------------------------------------
// Sampler: warp covers TWO queries; 16 lanes per query = 8 heads x 2 slots;
// slot covers 16 channels (2 x uint4 per corner). Full fp16 (HFMA2)
// interpolation AND accumulation; offsets pre-scaled in pack.
// ---------------------------------------------------------------------------
__global__ __launch_bounds__(256) void sample_kernel16(const float* __restrict__ ref)
{
    const int gw   = (blockIdx.x * 256 + threadIdx.x) >> 5;   // warp id
    const int lane = threadIdx.x & 31;
    const int m  = gw * 2 + (lane >> 4);
    const int hs = lane & 15;
    const int h  = hs >> 1;
    const int s  = hs & 1;
    const int b  = m >> 14;

    const float rx = __ldg(&ref[2 * m + 0]);
    const float ry = __ldg(&ref[2 * m + 1]);

    const float* qp = g_qp + (size_t)m * 96;

    const float4 lg = *(const float4*)(qp + 64 + h * 4);
    const float mxl = fmaxf(fmaxf(lg.x, lg.y), fmaxf(lg.z, lg.w));
    const float e0 = __expf(lg.x - mxl), e1 = __expf(lg.y - mxl);
    const float e2 = __expf(lg.z - mxl), e3 = __expf(lg.w - mxl);
    const float inv = 1.f / (e0 + e1 + e2 + e3);
    const float w4[4] = {e0 * inv, e1 * inv, e2 * inv, e3 * inv};

    const float4 o01 = *(const float4*)(qp + h * 8);
    const float4 o23 = *(const float4*)(qp + h * 8 + 4);
    const float offx[4] = {o01.x, o01.z, o23.x, o23.z};   // pre-scaled
    const float offy[4] = {o01.y, o01.w, o23.y, o23.w};

    const __half* vb = g_vproj_h + (size_t)b * HW_ * C_ + h * HD_ + s * 16;

    __half2 acc[8];
    #pragma unroll
    for (int q = 0; q < 8; q++) acc[q] = __half2half2(__float2half(0.f));

    #pragma unroll
    for (int p = 0; p < 4; p++) {
        const float lx = fminf(fmaxf(rx + offx[p], 0.f), 1.f);
        const float ly = fminf(fmaxf(ry + offy[p], 0.f), 1.f);
        const float ixf = lx * (float)W_ - 0.5f;
        const float iyf = ly * (float)H_ - 0.5f;
        const float x0f = floorf(ixf), y0f = floorf(iyf);
        const float wx = ixf - x0f, wy = iyf - y0f;
        const int x0 = (int)x0f, y0 = (int)y0f;    // in [-1,127]

        const float cx0 = (x0 >= 0)      ? 1.f - wx : 0.f;
        const float cx1 = (x0 < W_ - 1)  ? wx       : 0.f;
        const float wp  = w4[p];
        const float cy0 = (y0 >= 0)      ? wp * (1.f - wy) : 0.f;
        const float cy1 = (y0 < H_ - 1)  ? wp * wy         : 0.f;

        const int x0c = max(x0, 0),     x1c = min(x0 + 1, W_ - 1);
        const int y0c = max(y0, 0),     y1c = min(y0 + 1, H_ - 1);

        const __half2 c00 = __float2half2_rn(cx0 * cy0);
        const __half2 c10 = __float2half2_rn(cx1 * cy0);
        const __half2 c01 = __float2half2_rn(cx0 * cy1);
        const __half2 c11 = __float2half2_rn(cx1 * cy1);

        const __half* p00 = vb + (size_t)(y0c * W_ + x0c) * C_;
        const __half* p10 = vb + (size_t)(y0c * W_ + x1c) * C_;
        const __half* p01 = vb + (size_t)(y1c * W_ + x0c) * C_;
        const __half* p11 = vb + (size_t)(y1c * W_ + x1c) * C_;

        const uint4 a00 = *(const uint4*)(p00), b00 = *(const uint4*)(p00 + 8);
        const uint4 a10 = *(const uint4*)(p10), b10 = *(const uint4*)(p10 + 8);
        const uint4 a01 = *(const uint4*)(p01), b01 = *(const uint4*)(p01 + 8);
        const uint4 a11 = *(const uint4*)(p11), b11 = *(const uint4*)(p11 + 8);

        #pragma unroll
        for (int q = 0; q < 4; q++) {
            acc[q] = __hfma2(c00, ((const __half2*)&a00)[q],
                     __hfma2(c10, ((const __half2*)&a10)[q],
                     __hfma2(c01, ((const __half2*)&a01)[q],
                     __hfma2(c11, ((const __half2*)&a11)[q], acc[q]))));
            acc[4 + q] = __hfma2(c00, ((const __half2*)&b00)[q],
                         __hfma2(c10, ((const __half2*)&b10)[q],
                         __hfma2(c01, ((const __half2*)&b01)[q],
                         __hfma2(c11, ((const __half2*)&b11)[q], acc[4 + q]))));
        }
    }

    __half* dst = g_sampled_h + (size_t)m * C_ + h * HD_ + s * 16;
    *(uint4*)(dst)     = *(const uint4*)&acc[0];
    *(uint4*)(dst + 8) = *(const uint4*)&acc[4];
}

// ---------------------------------------------------------------------------
extern "C" void kernel_launch(void* const* d_in, const int* in_sizes, int n_in,
                              void* d_out, int out_size)
{
    const float* query  = (const float*)d_in[0];
    const float* refp   = (const float*)d_in[1];
    const float* value  = (const float*)d_in[2];
    const float* W_off  = (const float*)d_in[3];
    const float* b_off  = (const float*)d_in[4];
    const float* W_attn = (const float*)d_in[5];
    const float* b_attn = (const float*)d_in[6];
    const float* W_v    = (const float*)d_in[7];
    const float* b_v    = (const float*)d_in[8];
    const float* W_out  = (const float*)d_in[9];
    const float* b_out  = (const float*)d_in[10];
    float* out = (float*)d_out;

    cudaFuncSetAttribute(fused_qpvp, cudaFuncAttributeMaxDynamicSharedMemorySize, SMEM_QPVP);
    cudaFuncSetAttribute(out_gemm,   cudaFuncAttributeMaxDynamicSharedMemorySize, SMEM_OUT);

    // 0) pack/transpose/convert all weights (offset weights pre-scaled)
    pack_all<<<608, 256>>>(W_v, W_out, W_off, b_off, W_attn, b_attn);
    // 1+2) fused offset/logit projection + value projection
    fused_qpvp<<<dim3(3, M_ / 128), 128, SMEM_QPVP>>>(query, value, b_v);
    // 3) softmax + bilinear deformable sampling (fp16 throughout)
    sample_kernel16<<<M_ / 16, 256>>>(refp);
    // 4) output projection (fp16 A) -> d_out
    out_gemm<<<dim3(2, M_ / 128), 128, SMEM_OUT>>>(b_out, out);
}